// round 14
// baseline (speedup 1.0000x reference)
#include <cuda_runtime.h>
#include <cuda_fp16.h>
#include <math.h>

#define NB    4
#define NPTS  8192
#define NP    (NB*NPTS)          /* 32768 points */
#define KNN   32
#define NE    (NB*NPTS*KNN)      /* 1048576 edges */
#define EPB   (NPTS*KNN)         /* 262144 edges per batch */
#define BC    256
#define CNTF  ((float)EPB)
#define EPSV  1e-5f
#define SLOPE 0.1f

// Y stored fp16: 32 half2-planes; plane p holds channels (2p, 2p+1) per edge
__device__ unsigned g_Y16[(size_t)32 * NE];
__device__ __align__(16) float g_sum[BC], g_sumsq[BC], g_s[BC], g_t[BC];
// pre-split weights (bf16x2 hi/lo)
__device__ __align__(16) unsigned g_Wh[2][2048], g_Wl[2][2048];
__device__ __align__(16) unsigned g_W1h[64*18], g_W1l[64*18];
// stage-3 pooled raw y: [point][64ch], max and min
__device__ __align__(16) float g_Pmx[(size_t)NP*64], g_Pmn[(size_t)NP*64];

// ---------------------------------------------------------------- helpers
__device__ __forceinline__ uint2 split2(float x0, float x1) {
    unsigned h, l;
    asm("cvt.rn.bf16x2.f32 %0, %1, %2;" : "=r"(h) : "f"(x1), "f"(x0));
    float h0 = __uint_as_float(h << 16);
    float h1 = __uint_as_float(h & 0xffff0000u);
    asm("cvt.rn.bf16x2.f32 %0, %1, %2;" : "=r"(l) : "f"(x1 - h1), "f"(x0 - h0));
    return make_uint2(h, l);
}
__device__ __forceinline__ void mma16(float* c,
                                      unsigned a0, unsigned a1, unsigned a2, unsigned a3,
                                      unsigned b0, unsigned b1) {
    asm("mma.sync.aligned.m16n8k16.row.col.f32.bf16.bf16.f32 "
        "{%0,%1,%2,%3},{%4,%5,%6,%7},{%8,%9},{%0,%1,%2,%3};"
        : "+f"(c[0]), "+f"(c[1]), "+f"(c[2]), "+f"(c[3])
        : "r"(a0), "r"(a1), "r"(a2), "r"(a3), "r"(b0), "r"(b1));
}
__device__ __forceinline__ void ldsm4(unsigned& r0, unsigned& r1,
                                      unsigned& r2, unsigned& r3, unsigned a) {
    asm volatile("ldmatrix.sync.aligned.m8n8.x4.shared.b16 {%0,%1,%2,%3}, [%4];"
        : "=r"(r0), "=r"(r1), "=r"(r2), "=r"(r3) : "r"(a));
}
__device__ __forceinline__ unsigned s2u(const void* p) {
    return (unsigned)__cvta_generic_to_shared(p);
}

// -------------------------------- prep: zero stats + pre-split all weights
__global__ void k_prep(const float* __restrict__ W1,
                       const float* __restrict__ W2,
                       const float* __restrict__ W3) {
    int tid = threadIdx.x;
    if (tid < BC) { g_sum[tid] = 0.f; g_sumsq[tid] = 0.f; }
    for (int p = tid; p < 2048; p += 256) {
        int o = p >> 5, cp = p & 31;
        float2 w2 = *(const float2*)&W2[o*64 + 2*cp];
        uint2 a = split2(w2.x, w2.y);
        g_Wh[0][p] = a.x; g_Wl[0][p] = a.y;
        float2 w3 = *(const float2*)&W3[o*64 + 2*cp];
        uint2 b = split2(w3.x, w3.y);
        g_Wh[1][p] = b.x; g_Wl[1][p] = b.y;
    }
    for (int p = tid; p < 64*18; p += 256) {
        int o = p / 18, cp = p - o*18;
        float w0, w1;
        if (cp < 17)      { w0 = W1[o*35 + 2*cp]; w1 = W1[o*35 + 2*cp + 1]; }
        else              { w0 = W1[o*35 + 34];   w1 = 0.f; }
        uint2 hl = split2(w0, w1);
        g_W1h[p] = hl.x; g_W1l[p] = hl.y;
    }
}

// ------ shared stats piece: warp-reduce s/q, atomics into sStat, then global
__device__ __forceinline__ void stats_reduce(float acc[2][4][4], int b, float* sStat) {
    int tid = threadIdx.x;
    int lane = tid & 31, wid = tid >> 5;
    int n0 = (wid >> 2) * 32;
    float s8[8], q8[8];
    #pragma unroll
    for (int nt = 0; nt < 4; nt++) {
        #pragma unroll
        for (int par = 0; par < 2; par++) {
            float a = acc[0][nt][par],   c = acc[0][nt][par+2];
            float d = acc[1][nt][par],   e = acc[1][nt][par+2];
            s8[nt*2+par] = (a + c) + (d + e);
            q8[nt*2+par] = fmaf(a,a, fmaf(c,c, fmaf(d,d, e*e)));
        }
    }
    #pragma unroll
    for (int off = 16; off >= 4; off >>= 1) {
        #pragma unroll
        for (int i = 0; i < 8; i++) {
            s8[i] += __shfl_down_sync(0xffffffffu, s8[i], off);
            q8[i] += __shfl_down_sync(0xffffffffu, q8[i], off);
        }
    }
    if (lane < 4) {
        #pragma unroll
        for (int nt = 0; nt < 4; nt++) {
            #pragma unroll
            for (int par = 0; par < 2; par++) {
                int ch = n0 + nt*8 + 2*lane + par;
                atomicAdd(&sStat[ch], s8[nt*2+par]);
                atomicAdd(&sStat[64+ch], q8[nt*2+par]);
            }
        }
    }
    __syncthreads();
    if (tid < 128) {
        float v = sStat[tid];
        if (tid < 64) atomicAdd(&g_sum[b*64 + tid], v);
        else          atomicAdd(&g_sumsq[b*64 + tid - 64], v);
    }
}

// ------ epilogue A: store fp16 Y planes + stats (stages 1 and 2)
__device__ __forceinline__ void mma_epilogue(float acc[2][4][4], size_t bb, int b,
                                             float* sStat) {
    int tid = threadIdx.x;
    int lane = tid & 31, wid = tid >> 5;
    int gid = lane >> 2, tig = lane & 3;
    int m0 = (wid & 3) * 32, n0 = (wid >> 2) * 32;
    #pragma unroll
    for (int mt = 0; mt < 2; mt++) {
        #pragma unroll
        for (int nt = 0; nt < 4; nt++) {
            int pl = (n0 >> 1) + nt*4 + tig;          // half2 plane
            size_t eg = bb + m0 + mt*16 + gid;
            __half2 h01 = __floats2half2_rn(acc[mt][nt][0], acc[mt][nt][1]);
            __half2 h23 = __floats2half2_rn(acc[mt][nt][2], acc[mt][nt][3]);
            g_Y16[(size_t)pl*NE + eg]     = *(unsigned*)&h01;
            g_Y16[(size_t)pl*NE + eg + 8] = *(unsigned*)&h23;
        }
    }
    stats_reduce(acc, b, sStat);
}

// ------ epilogue B: pooled min/max per point (stage 3; skips Y entirely)
__device__ __forceinline__ void mma_epilogue_pool(float acc[2][4][4], size_t bp, int b,
                                                  float* sStat) {
    int tid = threadIdx.x;
    int lane = tid & 31, wid = tid >> 5;
    int n0 = (wid >> 2) * 32, wm = wid & 3;
    float mx8[8], mn8[8];
    #pragma unroll
    for (int nt = 0; nt < 4; nt++) {
        #pragma unroll
        for (int par = 0; par < 2; par++) {
            float a = acc[0][nt][par],   c = acc[0][nt][par+2];
            float d = acc[1][nt][par],   e = acc[1][nt][par+2];
            mx8[nt*2+par] = fmaxf(fmaxf(a,c), fmaxf(d,e));
            mn8[nt*2+par] = fminf(fminf(a,c), fminf(d,e));
        }
    }
    #pragma unroll
    for (int off = 16; off >= 4; off >>= 1) {
        #pragma unroll
        for (int i = 0; i < 8; i++) {
            mx8[i] = fmaxf(mx8[i], __shfl_down_sync(0xffffffffu, mx8[i], off));
            mn8[i] = fminf(mn8[i], __shfl_down_sync(0xffffffffu, mn8[i], off));
        }
    }
    if (lane < 4) {
        size_t pt = bp + wm;
        #pragma unroll
        for (int nt = 0; nt < 4; nt++) {
            #pragma unroll
            for (int par = 0; par < 2; par++) {
                int ch = n0 + nt*8 + 2*lane + par;
                g_Pmx[pt*64 + ch] = mx8[nt*2+par];
                g_Pmn[pt*64 + ch] = mn8[nt*2+par];
            }
        }
    }
    stats_reduce(acc, b, sStat);
}

// smem layout, stride 36 words (conflict-free; 144B rows, 16B aligned)
#define PSTR 36
#define OFF_XH 0
#define OFF_XL (128*PSTR)
#define OFF_WH (256*PSTR)
#define OFF_WL (256*PSTR + 64*PSTR)
#define OFF_ST (256*PSTR + 128*PSTR)
#define STAGE_SMEM ((384*PSTR + 128) * (int)sizeof(unsigned))

// ---------------- common bf16 mma mainloop (LDSM fragment loads) ----------
template<int NCHUNK>
__device__ __forceinline__ void mma_main(const unsigned* sm, float acc[2][4][4]) {
    int tid = threadIdx.x;
    int lane = tid & 31, wid = tid >> 5;
    int m0 = (wid & 3) * 32, n0 = (wid >> 2) * 32;
    int g = lane >> 3, lr = lane & 7;

    int arow = m0 + lr + (g & 1)*8;
    int acol = (g >> 1)*4;
    unsigned aH0 = s2u(sm + OFF_XH + arow*PSTR + acol);
    unsigned aH1 = aH0 + 16*PSTR*4;
    unsigned aL0 = aH0 + (OFF_XL - OFF_XH)*4;
    unsigned aL1 = aH1 + (OFF_XL - OFF_XH)*4;
    int brow = n0 + lr + (g >> 1)*8;
    int bcol = (g & 1)*4;
    unsigned bH0 = s2u(sm + OFF_WH + brow*PSTR + bcol);
    unsigned bH1 = bH0 + 16*PSTR*4;
    unsigned bL0 = bH0 + 64*PSTR*4;
    unsigned bL1 = bH1 + 64*PSTR*4;

    #pragma unroll
    for (int mt = 0; mt < 2; mt++)
        #pragma unroll
        for (int nt = 0; nt < 4; nt++)
            #pragma unroll
            for (int r = 0; r < 4; r++) acc[mt][nt][r] = 0.f;

    #pragma unroll
    for (int ks = 0; ks < NCHUNK; ks++) {
        unsigned off = ks*32;
        unsigned ah[2][4], al[2][4], bh[4][2], bl[4][2];
        ldsm4(ah[0][0], ah[0][1], ah[0][2], ah[0][3], aH0 + off);
        ldsm4(ah[1][0], ah[1][1], ah[1][2], ah[1][3], aH1 + off);
        ldsm4(al[0][0], al[0][1], al[0][2], al[0][3], aL0 + off);
        ldsm4(al[1][0], al[1][1], al[1][2], al[1][3], aL1 + off);
        ldsm4(bh[0][0], bh[0][1], bh[1][0], bh[1][1], bH0 + off);
        ldsm4(bh[2][0], bh[2][1], bh[3][0], bh[3][1], bH1 + off);
        ldsm4(bl[0][0], bl[0][1], bl[1][0], bl[1][1], bL0 + off);
        ldsm4(bl[2][0], bl[2][1], bl[3][0], bl[3][1], bL1 + off);
        #pragma unroll
        for (int mt = 0; mt < 2; mt++)
            #pragma unroll
            for (int nt = 0; nt < 4; nt++) {
                mma16(acc[mt][nt], ah[mt][0],ah[mt][1],ah[mt][2],ah[mt][3], bh[nt][0],bh[nt][1]);
                mma16(acc[mt][nt], ah[mt][0],ah[mt][1],ah[mt][2],ah[mt][3], bl[nt][0],bl[nt][1]);
                mma16(acc[mt][nt], al[mt][0],al[mt][1],al[mt][2],al[mt][3], bh[nt][0],bh[nt][1]);
            }
    }
}

// ------- stage 1: gather + concat + GEMM1 (K=35 padded to 48, 3 chunks)
__global__ void __launch_bounds__(256) k_stage1(
    const float* __restrict__ signal, const int* __restrict__ edges,
    const float* __restrict__ efeat)
{
    extern __shared__ unsigned sm[];
    float* sStat = (float*)(sm + OFF_ST);

    int tid = threadIdx.x;
    int b = blockIdx.x >> 11;
    size_t bb = (size_t)blockIdx.x * 128;

    #pragma unroll
    for (int i = tid; i < 64*9; i += 256) {
        int o = i / 9, j = i - o*9;
        uint2 h = *(const uint2*)&g_W1h[o*18 + j*2];
        uint2 l = *(const uint2*)&g_W1l[o*18 + j*2];
        *(uint2*)&sm[OFF_WH + o*PSTR + j*2] = h;
        *(uint2*)&sm[OFF_WL + o*PSTR + j*2] = l;
    }
    for (int i = tid; i < 128*6; i += 256) {
        int e = i / 6, cp = 18 + (i - (i/6)*6);
        sm[OFF_XH + e*PSTR + cp] = 0u; sm[OFF_XL + e*PSTR + cp] = 0u;
    }
    for (int i = tid; i < 64*6; i += 256) {
        int o = i / 6, cp = 18 + (i - (i/6)*6);
        sm[OFF_WH + o*PSTR + cp] = 0u; sm[OFF_WL + o*PSTR + cp] = 0u;
    }
    if (tid < 128) sStat[tid] = 0.f;

    {
        int eL = tid >> 1, part = tid & 1;
        int idx = edges[bb + eL];
        const float4* src = (const float4*)signal + (size_t)idx*8 + part*4;
        #pragma unroll
        for (int q = 0; q < 4; q++) {
            float4 v = src[q];
            uint2 h0 = split2(v.x, v.y);
            uint2 h1 = split2(v.z, v.w);
            int cp = part*8 + q*2;
            sm[OFF_XH + eL*PSTR + cp]     = h0.x; sm[OFF_XL + eL*PSTR + cp]     = h0.y;
            sm[OFF_XH + eL*PSTR + cp + 1] = h1.x; sm[OFF_XL + eL*PSTR + cp + 1] = h1.y;
        }
    }
    if (tid < 128) {
        size_t base = 3*(bb + tid);
        float f0 = efeat[base], f1 = efeat[base+1], f2 = efeat[base+2];
        uint2 h0 = split2(f0, f1);
        uint2 h1 = split2(f2, 0.f);
        sm[OFF_XH + tid*PSTR + 16] = h0.x; sm[OFF_XL + tid*PSTR + 16] = h0.y;
        sm[OFF_XH + tid*PSTR + 17] = h1.x; sm[OFF_XL + tid*PSTR + 17] = h1.y;
    }
    __syncthreads();

    float acc[2][4][4];
    mma_main<3>(sm, acc);
    mma_epilogue(acc, bb, b, sStat);
}

// ------------------------------------- stats -> (scale, shift), reset accum
__global__ void k_finalize(const float* __restrict__ gam, const float* __restrict__ bet) {
    int i = threadIdx.x;
    float mean = g_sum[i]   * (1.f/CNTF);
    float var  = g_sumsq[i] * (1.f/CNTF) - mean*mean;
    float sc   = gam[i & 63] * rsqrtf(var + EPSV);
    g_s[i] = sc;
    g_t[i] = bet[i & 63] - mean * sc;
    g_sum[i] = 0.f; g_sumsq[i] = 0.f;
}

// ------- stages 2/3: norm + leaky + 64x64 GEMM (K=64, 4 chunks)
template<int POOL>
__global__ void __launch_bounds__(256, 4) k_stage(int wsel) {
    extern __shared__ unsigned sm[];
    float* sStat = (float*)(sm + OFF_ST);

    int tid = threadIdx.x;
    int b = blockIdx.x >> 11;
    size_t bb = (size_t)blockIdx.x * 128;

    const unsigned* wh = g_Wh[wsel];
    const unsigned* wl = g_Wl[wsel];
    #pragma unroll
    for (int i = tid; i < 512; i += 256) {
        int o = i >> 3, j = i & 7;
        uint4 h = *(const uint4*)&wh[o*32 + j*4];
        uint4 l = *(const uint4*)&wl[o*32 + j*4];
        *(uint4*)&sm[OFF_WH + o*PSTR + j*4] = h;
        *(uint4*)&sm[OFF_WL + o*PSTR + j*4] = l;
    }
    if (tid < 128) sStat[tid] = 0.f;

    // X: read fp16 planes, normalize + leaky, split, store pairs
    #pragma unroll
    for (int i = tid; i < 4096; i += 256) {       // 16 iters
        int p = i >> 7, eL = i & 127;
        unsigned hv = g_Y16[(size_t)p*NE + bb + eL];
        __half2 hh = *(__half2*)&hv;
        float2 v = __half22float2(hh);
        float2 sc = __ldg(&((const float2*)g_s)[b*32 + p]);
        float2 tt = __ldg(&((const float2*)g_t)[b*32 + p]);
        float x0 = fmaf(v.x, sc.x, tt.x); x0 = (x0>=0.f)?x0:SLOPE*x0;
        float x1 = fmaf(v.y, sc.y, tt.y); x1 = (x1>=0.f)?x1:SLOPE*x1;
        uint2 hl = split2(x0, x1);
        sm[OFF_XH + eL*PSTR + p] = hl.x;
        sm[OFF_XL + eL*PSTR + p] = hl.y;
    }
    __syncthreads();

    float acc[2][4][4];
    mma_main<4>(sm, acc);
    if (POOL) mma_epilogue_pool(acc, (size_t)blockIdx.x * 4, b, sStat);
    else      mma_epilogue(acc, bb, b, sStat);
}

// -------- final: norm3 + leaky on pooled extrema, direct (B,N,64) store
__global__ void __launch_bounds__(256) k_out(float* __restrict__ out) {
    int tid = blockIdx.x * 256 + threadIdx.x;    // over NP*16 float4s
    int c4 = tid & 15;
    int pt = tid >> 4;
    int b  = pt >> 13;
    float4 sc = ((const float4*)g_s)[b*16 + c4];
    float4 tt = ((const float4*)g_t)[b*16 + c4];
    float4 mx = ((const float4*)g_Pmx)[tid];
    float4 mn = ((const float4*)g_Pmn)[tid];
    float4 y;
    y.x = fmaf((sc.x>=0.f)?mx.x:mn.x, sc.x, tt.x); y.x = (y.x>=0.f)?y.x:SLOPE*y.x;
    y.y = fmaf((sc.y>=0.f)?mx.y:mn.y, sc.y, tt.y); y.y = (y.y>=0.f)?y.y:SLOPE*y.y;
    y.z = fmaf((sc.z>=0.f)?mx.z:mn.z, sc.z, tt.z); y.z = (y.z>=0.f)?y.z:SLOPE*y.z;
    y.w = fmaf((sc.w>=0.f)?mx.w:mn.w, sc.w, tt.w); y.w = (y.w>=0.f)?y.w:SLOPE*y.w;
    ((float4*)out)[tid] = y;
}

// ---------------------------------------------------------------------------
extern "C" void kernel_launch(void* const* d_in, const int* in_sizes, int n_in,
                              void* d_out, int out_size)
{
    const float* signal = (const float*)d_in[0];
    const int*   edges  = (const int*)d_in[1];
    const float* efeat  = (const float*)d_in[2];
    // d_in[3] = k (constant 32, baked in)
    const float* W1 = (const float*)d_in[4];
    const float* g1 = (const float*)d_in[5];
    const float* b1 = (const float*)d_in[6];
    const float* W2 = (const float*)d_in[7];
    const float* g2 = (const float*)d_in[8];
    const float* b2 = (const float*)d_in[9];
    const float* W3 = (const float*)d_in[10];
    const float* g3 = (const float*)d_in[11];
    const float* b3 = (const float*)d_in[12];
    float* out = (float*)d_out;

    cudaFuncSetAttribute(k_stage1,   cudaFuncAttributeMaxDynamicSharedMemorySize, STAGE_SMEM);
    cudaFuncSetAttribute(k_stage<0>, cudaFuncAttributeMaxDynamicSharedMemorySize, STAGE_SMEM);
    cudaFuncSetAttribute(k_stage<1>, cudaFuncAttributeMaxDynamicSharedMemorySize, STAGE_SMEM);

    k_prep<<<1, 256>>>(W1, W2, W3);
    k_stage1<<<NE/128, 256, STAGE_SMEM>>>(signal, edges, efeat);
    k_finalize<<<1, 256>>>(g1, b1);
    k_stage<0><<<NE/128, 256, STAGE_SMEM>>>(0);
    k_finalize<<<1, 256>>>(g2, b2);
    k_stage<1><<<NE/128, 256, STAGE_SMEM>>>(1);
    k_finalize<<<1, 256>>>(g3, b3);
    k_out<<<(NP*16)/256, 256>>>(out);
}

// round 15
// speedup vs baseline: 1.2109x; 1.2109x over previous
#include <cuda_runtime.h>
#include <cuda_fp16.h>
#include <math.h>

#define NB    4
#define NPTS  8192
#define NP    (NB*NPTS)          /* 32768 points */
#define KNN   32
#define NE    (NB*NPTS*KNN)      /* 1048576 edges */
#define EPB   (NPTS*KNN)         /* 262144 edges per batch */
#define BC    256
#define CNTF  ((float)EPB)
#define EPSV  1e-5f
#define SLOPE 0.1f

// Y fp16, granule-major: granule q (0..7) = channels [8q,8q+8) of an edge,
// stored as uint4 (4 half2 words). word index = (q*NE + e)*4 + w, w=plane&3.
__device__ __align__(16) unsigned g_Y16[(size_t)32 * NE];
__device__ __align__(16) float g_sum[BC], g_sumsq[BC], g_s[BC], g_t[BC];
// pre-split weights (bf16x2 hi/lo)
__device__ __align__(16) unsigned g_Wh[2][2048], g_Wl[2][2048];
__device__ __align__(16) unsigned g_W1h[64*18], g_W1l[64*18];
// stage-3 pooled raw y: [point][64ch], max and min
__device__ __align__(16) float g_Pmx[(size_t)NP*64], g_Pmn[(size_t)NP*64];

// ---------------------------------------------------------------- helpers
__device__ __forceinline__ uint2 split2(float x0, float x1) {
    unsigned h, l;
    asm("cvt.rn.bf16x2.f32 %0, %1, %2;" : "=r"(h) : "f"(x1), "f"(x0));
    float h0 = __uint_as_float(h << 16);
    float h1 = __uint_as_float(h & 0xffff0000u);
    asm("cvt.rn.bf16x2.f32 %0, %1, %2;" : "=r"(l) : "f"(x1 - h1), "f"(x0 - h0));
    return make_uint2(h, l);
}
__device__ __forceinline__ void mma16(float* c,
                                      unsigned a0, unsigned a1, unsigned a2, unsigned a3,
                                      unsigned b0, unsigned b1) {
    asm("mma.sync.aligned.m16n8k16.row.col.f32.bf16.bf16.f32 "
        "{%0,%1,%2,%3},{%4,%5,%6,%7},{%8,%9},{%0,%1,%2,%3};"
        : "+f"(c[0]), "+f"(c[1]), "+f"(c[2]), "+f"(c[3])
        : "r"(a0), "r"(a1), "r"(a2), "r"(a3), "r"(b0), "r"(b1));
}
__device__ __forceinline__ void ldsm4(unsigned& r0, unsigned& r1,
                                      unsigned& r2, unsigned& r3, unsigned a) {
    asm volatile("ldmatrix.sync.aligned.m8n8.x4.shared.b16 {%0,%1,%2,%3}, [%4];"
        : "=r"(r0), "=r"(r1), "=r"(r2), "=r"(r3) : "r"(a));
}
__device__ __forceinline__ unsigned s2u(const void* p) {
    return (unsigned)__cvta_generic_to_shared(p);
}

// -------------------------------- prep: zero stats + pre-split all weights
__global__ void k_prep(const float* __restrict__ W1,
                       const float* __restrict__ W2,
                       const float* __restrict__ W3) {
    int tid = threadIdx.x;
    if (tid < BC) { g_sum[tid] = 0.f; g_sumsq[tid] = 0.f; }
    for (int p = tid; p < 2048; p += 256) {
        int o = p >> 5, cp = p & 31;
        float2 w2 = *(const float2*)&W2[o*64 + 2*cp];
        uint2 a = split2(w2.x, w2.y);
        g_Wh[0][p] = a.x; g_Wl[0][p] = a.y;
        float2 w3 = *(const float2*)&W3[o*64 + 2*cp];
        uint2 b = split2(w3.x, w3.y);
        g_Wh[1][p] = b.x; g_Wl[1][p] = b.y;
    }
    for (int p = tid; p < 64*18; p += 256) {
        int o = p / 18, cp = p - o*18;
        float w0, w1;
        if (cp < 17)      { w0 = W1[o*35 + 2*cp]; w1 = W1[o*35 + 2*cp + 1]; }
        else              { w0 = W1[o*35 + 34];   w1 = 0.f; }
        uint2 hl = split2(w0, w1);
        g_W1h[p] = hl.x; g_W1l[p] = hl.y;
    }
}

// ------ shared stats piece: warp-reduce s/q, atomics into sStat, then global
__device__ __forceinline__ void stats_reduce(float acc[2][4][4], int b, float* sStat) {
    int tid = threadIdx.x;
    int lane = tid & 31, wid = tid >> 5;
    int n0 = (wid >> 2) * 32;
    float s8[8], q8[8];
    #pragma unroll
    for (int nt = 0; nt < 4; nt++) {
        #pragma unroll
        for (int par = 0; par < 2; par++) {
            float a = acc[0][nt][par],   c = acc[0][nt][par+2];
            float d = acc[1][nt][par],   e = acc[1][nt][par+2];
            s8[nt*2+par] = (a + c) + (d + e);
            q8[nt*2+par] = fmaf(a,a, fmaf(c,c, fmaf(d,d, e*e)));
        }
    }
    #pragma unroll
    for (int off = 16; off >= 4; off >>= 1) {
        #pragma unroll
        for (int i = 0; i < 8; i++) {
            s8[i] += __shfl_down_sync(0xffffffffu, s8[i], off);
            q8[i] += __shfl_down_sync(0xffffffffu, q8[i], off);
        }
    }
    if (lane < 4) {
        #pragma unroll
        for (int nt = 0; nt < 4; nt++) {
            #pragma unroll
            for (int par = 0; par < 2; par++) {
                int ch = n0 + nt*8 + 2*lane + par;
                atomicAdd(&sStat[ch], s8[nt*2+par]);
                atomicAdd(&sStat[64+ch], q8[nt*2+par]);
            }
        }
    }
    __syncthreads();
    if (tid < 128) {
        float v = sStat[tid];
        if (tid < 64) atomicAdd(&g_sum[b*64 + tid], v);
        else          atomicAdd(&g_sumsq[b*64 + tid - 64], v);
    }
}

// ------ epilogue A: store fp16 Y (granule layout, coalesced) + stats
__device__ __forceinline__ void mma_epilogue(float acc[2][4][4], size_t bb, int b,
                                             float* sStat) {
    int tid = threadIdx.x;
    int lane = tid & 31, wid = tid >> 5;
    int gid = lane >> 2, tig = lane & 3;
    int m0 = (wid & 3) * 32, n0 = (wid >> 2) * 32;
    #pragma unroll
    for (int mt = 0; mt < 2; mt++) {
        #pragma unroll
        for (int nt = 0; nt < 4; nt++) {
            int qn = (n0 >> 3) + nt;                  // granule
            size_t eg = bb + m0 + mt*16 + gid;
            __half2 h01 = __floats2half2_rn(acc[mt][nt][0], acc[mt][nt][1]);
            __half2 h23 = __floats2half2_rn(acc[mt][nt][2], acc[mt][nt][3]);
            size_t w0 = ((size_t)qn*NE + eg)*4 + tig;
            g_Y16[w0]      = *(unsigned*)&h01;        // edge eg
            g_Y16[w0 + 32] = *(unsigned*)&h23;        // edge eg+8 -> +8*4 words
        }
    }
    stats_reduce(acc, b, sStat);
}

// ------ epilogue B: pooled min/max per point (stage 3; skips Y entirely)
__device__ __forceinline__ void mma_epilogue_pool(float acc[2][4][4], size_t bp, int b,
                                                  float* sStat) {
    int tid = threadIdx.x;
    int lane = tid & 31, wid = tid >> 5;
    int n0 = (wid >> 2) * 32, wm = wid & 3;
    float mx8[8], mn8[8];
    #pragma unroll
    for (int nt = 0; nt < 4; nt++) {
        #pragma unroll
        for (int par = 0; par < 2; par++) {
            float a = acc[0][nt][par],   c = acc[0][nt][par+2];
            float d = acc[1][nt][par],   e = acc[1][nt][par+2];
            mx8[nt*2+par] = fmaxf(fmaxf(a,c), fmaxf(d,e));
            mn8[nt*2+par] = fminf(fminf(a,c), fminf(d,e));
        }
    }
    #pragma unroll
    for (int off = 16; off >= 4; off >>= 1) {
        #pragma unroll
        for (int i = 0; i < 8; i++) {
            mx8[i] = fmaxf(mx8[i], __shfl_down_sync(0xffffffffu, mx8[i], off));
            mn8[i] = fminf(mn8[i], __shfl_down_sync(0xffffffffu, mn8[i], off));
        }
    }
    if (lane < 4) {
        size_t pt = bp + wm;
        #pragma unroll
        for (int nt = 0; nt < 4; nt++) {
            #pragma unroll
            for (int par = 0; par < 2; par++) {
                int ch = n0 + nt*8 + 2*lane + par;
                g_Pmx[pt*64 + ch] = mx8[nt*2+par];
                g_Pmn[pt*64 + ch] = mn8[nt*2+par];
            }
        }
    }
    stats_reduce(acc, b, sStat);
}

// smem: X swizzled PSTR=32 (granule XOR row&7); W stride 36 (LDSM-phase safe)
#define OFF_XH 0
#define OFF_XL 4096
#define OFF_WH 8192
#define OFF_WL (8192 + 64*36)
#define OFF_ST (8192 + 128*36)
#define STAGE_SMEM ((OFF_ST + 128) * (int)sizeof(unsigned))
#define PSTR 36   /* W rows only */

// ---------------- common bf16 mma mainloop (swizzled-X LDSM loads) --------
template<int NCHUNK>
__device__ __forceinline__ void mma_main(const unsigned* sm, float acc[2][4][4]) {
    int tid = threadIdx.x;
    int lane = tid & 31, wid = tid >> 5;
    int m0 = (wid & 3) * 32, n0 = (wid >> 2) * 32;
    int g = lane >> 3, lr = lane & 7;

    // A: swizzled X rows (128B/row)
    int arow = m0 + lr + (g & 1)*8;
    int r7 = arow & 7;
    int gbase = g >> 1;
    unsigned rowH = s2u(sm) + arow*128;
    unsigned rowL = rowH + OFF_XL*4;
    // B: W region, stride 36 words
    int brow = n0 + lr + (g >> 1)*8;
    int bcol = (g & 1)*4;
    unsigned bH0 = s2u(sm + OFF_WH + brow*PSTR + bcol);
    unsigned bH1 = bH0 + 16*PSTR*4;
    unsigned bL0 = bH0 + 64*PSTR*4;
    unsigned bL1 = bH1 + 64*PSTR*4;

    #pragma unroll
    for (int mt = 0; mt < 2; mt++)
        #pragma unroll
        for (int nt = 0; nt < 4; nt++)
            #pragma unroll
            for (int r = 0; r < 4; r++) acc[mt][nt][r] = 0.f;

    #pragma unroll
    for (int ks = 0; ks < NCHUNK; ks++) {
        unsigned gax = (unsigned)((gbase + 2*ks) ^ r7) << 4;   // swizzled granule byte off
        unsigned aH0 = rowH + gax, aH1 = aH0 + 16*128;
        unsigned aL0 = rowL + gax, aL1 = aL0 + 16*128;
        unsigned boff = ks*32;
        unsigned ah[2][4], al[2][4], bh[4][2], bl[4][2];
        ldsm4(ah[0][0], ah[0][1], ah[0][2], ah[0][3], aH0);
        ldsm4(ah[1][0], ah[1][1], ah[1][2], ah[1][3], aH1);
        ldsm4(al[0][0], al[0][1], al[0][2], al[0][3], aL0);
        ldsm4(al[1][0], al[1][1], al[1][2], al[1][3], aL1);
        ldsm4(bh[0][0], bh[0][1], bh[1][0], bh[1][1], bH0 + boff);
        ldsm4(bh[2][0], bh[2][1], bh[3][0], bh[3][1], bH1 + boff);
        ldsm4(bl[0][0], bl[0][1], bl[1][0], bl[1][1], bL0 + boff);
        ldsm4(bl[2][0], bl[2][1], bl[3][0], bl[3][1], bL1 + boff);
        #pragma unroll
        for (int mt = 0; mt < 2; mt++)
            #pragma unroll
            for (int nt = 0; nt < 4; nt++) {
                mma16(acc[mt][nt], ah[mt][0],ah[mt][1],ah[mt][2],ah[mt][3], bh[nt][0],bh[nt][1]);
                mma16(acc[mt][nt], ah[mt][0],ah[mt][1],ah[mt][2],ah[mt][3], bl[nt][0],bl[nt][1]);
                mma16(acc[mt][nt], al[mt][0],al[mt][1],al[mt][2],al[mt][3], bh[nt][0],bh[nt][1]);
            }
    }
}

// ------- stage 1: gather + concat + GEMM1 (K=35 padded to 48, 3 chunks)
__global__ void __launch_bounds__(256) k_stage1(
    const float* __restrict__ signal, const int* __restrict__ edges,
    const float* __restrict__ efeat)
{
    extern __shared__ unsigned sm[];
    float* sStat = (float*)(sm + OFF_ST);

    int tid = threadIdx.x;
    int b = blockIdx.x >> 11;
    size_t bb = (size_t)blockIdx.x * 128;

    // W1: pre-split pairs [64][18] into stride-36 rows + zero pads 18..23
    #pragma unroll
    for (int i = tid; i < 64*9; i += 256) {
        int o = i / 9, j = i - o*9;
        uint2 h = *(const uint2*)&g_W1h[o*18 + j*2];
        uint2 l = *(const uint2*)&g_W1l[o*18 + j*2];
        *(uint2*)&sm[OFF_WH + o*PSTR + j*2] = h;
        *(uint2*)&sm[OFF_WL + o*PSTR + j*2] = l;
    }
    for (int i = tid; i < 64*6; i += 256) {
        int o = i / 6, cp = 18 + (i - (i/6)*6);
        sm[OFF_WH + o*PSTR + cp] = 0u; sm[OFF_WL + o*PSTR + cp] = 0u;
    }
    if (tid < 128) sStat[tid] = 0.f;

    // gather: 2 threads per edge, 16 floats each -> 2 swizzled uint4 granules
    {
        int eL = tid >> 1, part = tid & 1;
        int idx = edges[bb + eL];
        const float4* src = (const float4*)signal + (size_t)idx*8 + part*4;
        float4 v0 = src[0], v1 = src[1], v2 = src[2], v3 = src[3];
        uint2 p0 = split2(v0.x, v0.y), p1 = split2(v0.z, v0.w);
        uint2 p2 = split2(v1.x, v1.y), p3 = split2(v1.z, v1.w);
        uint2 p4 = split2(v2.x, v2.y), p5 = split2(v2.z, v2.w);
        uint2 p6 = split2(v3.x, v3.y), p7 = split2(v3.z, v3.w);
        int e7 = eL & 7;
        unsigned wbase = eL*32;
        unsigned w0 = wbase + (((part*2 + 0) ^ e7) << 2);
        unsigned w1 = wbase + (((part*2 + 1) ^ e7) << 2);
        *(uint4*)&sm[OFF_XH + w0] = make_uint4(p0.x, p1.x, p2.x, p3.x);
        *(uint4*)&sm[OFF_XH + w1] = make_uint4(p4.x, p5.x, p6.x, p7.x);
        *(uint4*)&sm[OFF_XL + w0] = make_uint4(p0.y, p1.y, p2.y, p3.y);
        *(uint4*)&sm[OFF_XL + w1] = make_uint4(p4.y, p5.y, p6.y, p7.y);
    }
    if (tid < 128) {  // edge feats -> granule 4 (pairs 16,17 + zeros); granule 5 = 0
        size_t base = 3*(bb + tid);
        float f0 = efeat[base], f1 = efeat[base+1], f2 = efeat[base+2];
        uint2 h0 = split2(f0, f1);
        uint2 h1 = split2(f2, 0.f);
        int e7 = tid & 7;
        unsigned wbase = tid*32;
        unsigned w4 = wbase + ((4 ^ e7) << 2);
        unsigned w5 = wbase + ((5 ^ e7) << 2);
        *(uint4*)&sm[OFF_XH + w4] = make_uint4(h0.x, h1.x, 0u, 0u);
        *(uint4*)&sm[OFF_XL + w4] = make_uint4(h0.y, h1.y, 0u, 0u);
        *(uint4*)&sm[OFF_XH + w5] = make_uint4(0u, 0u, 0u, 0u);
        *(uint4*)&sm[OFF_XL + w5] = make_uint4(0u, 0u, 0u, 0u);
    }
    __syncthreads();

    float acc[2][4][4];
    mma_main<3>(sm, acc);
    mma_epilogue(acc, bb, b, sStat);
}

// ------------------------------------- stats -> (scale, shift), reset accum
__global__ void k_finalize(const float* __restrict__ gam, const float* __restrict__ bet) {
    int i = threadIdx.x;
    float mean = g_sum[i]   * (1.f/CNTF);
    float var  = g_sumsq[i] * (1.f/CNTF) - mean*mean;
    float sc   = gam[i & 63] * rsqrtf(var + EPSV);
    g_s[i] = sc;
    g_t[i] = bet[i & 63] - mean * sc;
    g_sum[i] = 0.f; g_sumsq[i] = 0.f;
}

// ------- stages 2/3: norm + leaky + 64x64 GEMM (K=64, 4 chunks)
template<int POOL>
__global__ void __launch_bounds__(256, 4) k_stage(int wsel) {
    extern __shared__ unsigned sm[];
    float* sStat = (float*)(sm + OFF_ST);

    int tid = threadIdx.x;
    int b = blockIdx.x >> 11;
    size_t bb = (size_t)blockIdx.x * 128;

    const unsigned* wh = g_Wh[wsel];
    const unsigned* wl = g_Wl[wsel];
    #pragma unroll
    for (int i = tid; i < 512; i += 256) {
        int o = i >> 3, j = i & 7;
        uint4 h = *(const uint4*)&wh[o*32 + j*4];
        uint4 l = *(const uint4*)&wl[o*32 + j*4];
        *(uint4*)&sm[OFF_WH + o*PSTR + j*4] = h;
        *(uint4*)&sm[OFF_WL + o*PSTR + j*4] = l;
    }
    if (tid < 128) sStat[tid] = 0.f;

    // X: vector-load fp16 granules, normalize + leaky, split, swizzled STS.128
    #pragma unroll
    for (int it = 0; it < 4; it++) {
        int i = it*256 + tid;
        int q = i >> 7, eL = i & 127;
        uint4 v = ((const uint4*)g_Y16)[(size_t)q*NE + bb + eL];
        float4 sA = __ldg(&((const float4*)g_s)[b*16 + 2*q]);
        float4 sB = __ldg(&((const float4*)g_s)[b*16 + 2*q + 1]);
        float4 tA = __ldg(&((const float4*)g_t)[b*16 + 2*q]);
        float4 tB = __ldg(&((const float4*)g_t)[b*16 + 2*q + 1]);
        float2 f0 = __half22float2(*(__half2*)&v.x);
        float2 f1 = __half22float2(*(__half2*)&v.y);
        float2 f2 = __half22float2(*(__half2*)&v.z);
        float2 f3 = __half22float2(*(__half2*)&v.w);
        float x0 = fmaf(f0.x, sA.x, tA.x); x0 = (x0>=0.f)?x0:SLOPE*x0;
        float x1 = fmaf(f0.y, sA.y, tA.y); x1 = (x1>=0.f)?x1:SLOPE*x1;
        float x2 = fmaf(f1.x, sA.z, tA.z); x2 = (x2>=0.f)?x2:SLOPE*x2;
        float x3 = fmaf(f1.y, sA.w, tA.w); x3 = (x3>=0.f)?x3:SLOPE*x3;
        float x4 = fmaf(f2.x, sB.x, tB.x); x4 = (x4>=0.f)?x4:SLOPE*x4;
        float x5 = fmaf(f2.y, sB.y, tB.y); x5 = (x5>=0.f)?x5:SLOPE*x5;
        float x6 = fmaf(f3.x, sB.z, tB.z); x6 = (x6>=0.f)?x6:SLOPE*x6;
        float x7 = fmaf(f3.y, sB.w, tB.w); x7 = (x7>=0.f)?x7:SLOPE*x7;
        uint2 p0 = split2(x0, x1), p1 = split2(x2, x3);
        uint2 p2 = split2(x4, x5), p3 = split2(x6, x7);
        unsigned wrd = eL*32 + ((q ^ (eL & 7)) << 2);
        *(uint4*)&sm[OFF_XH + wrd] = make_uint4(p0.x, p1.x, p2.x, p3.x);
        *(uint4*)&sm[OFF_XL + wrd] = make_uint4(p0.y, p1.y, p2.y, p3.y);
    }
    __syncthreads();

    float acc[2][4][4];
    mma_main<4>(sm, acc);
    if (POOL) mma_epilogue_pool(acc, (size_t)blockIdx.x * 4, b, sStat);
    else      mma_epilogue(acc, bb, b, sStat);
}

// -------- final: norm3 + leaky on pooled extrema, direct (B,N,64) store
__global__ void __launch_bounds__(256) k_out(float* __restrict__ out) {
    int tid = blockIdx.x * 256 + threadIdx.x;    // over NP*16 float4s
    int c4 = tid & 15;
    int pt = tid >> 4;
    int b  = pt >> 13;
    float4 sc = ((const float4*)g_s)[b*16 + c4];
    float4 tt = ((const float4*)g_t)[b*16 + c4];
    float4 mx = ((const float4*)g_Pmx)[tid];
    float4 mn = ((const float4*)g_Pmn)[tid];
    float4 y;
    y.x = fmaf((sc.x>=0.f)?mx.x:mn.x, sc.x, tt.x); y.x = (y.x>=0.f)?y.x:SLOPE*y.x;
    y.y = fmaf((sc.y>=0.f)?mx.y:mn.y, sc.y, tt.y); y.y = (y.y>=0.f)?y.y:SLOPE*y.y;
    y.z = fmaf((sc.z>=0.f)?mx.z:mn.z, sc.z, tt.z); y.z = (y.z>=0.f)?y.z:SLOPE*y.z;
    y.w = fmaf((sc.w>=0.f)?mx.w:mn.w, sc.w, tt.w); y.w = (y.w>=0.f)?y.w:SLOPE*y.w;
    ((float4*)out)[tid] = y;
}

// ---------------------------------------------------------------------------
extern "C" void kernel_launch(void* const* d_in, const int* in_sizes, int n_in,
                              void* d_out, int out_size)
{
    const float* signal = (const float*)d_in[0];
    const int*   edges  = (const int*)d_in[1];
    const float* efeat  = (const float*)d_in[2];
    // d_in[3] = k (constant 32, baked in)
    const float* W1 = (const float*)d_in[4];
    const float* g1 = (const float*)d_in[5];
    const float* b1 = (const float*)d_in[6];
    const float* W2 = (const float*)d_in[7];
    const float* g2 = (const float*)d_in[8];
    const float* b2 = (const float*)d_in[9];
    const float* W3 = (const float*)d_in[10];
    const float* g3 = (const float*)d_in[11];
    const float* b3 = (const float*)d_in[12];
    float* out = (float*)d_out;

    cudaFuncSetAttribute(k_stage1,   cudaFuncAttributeMaxDynamicSharedMemorySize, STAGE_SMEM);
    cudaFuncSetAttribute(k_stage<0>, cudaFuncAttributeMaxDynamicSharedMemorySize, STAGE_SMEM);
    cudaFuncSetAttribute(k_stage<1>, cudaFuncAttributeMaxDynamicSharedMemorySize, STAGE_SMEM);

    k_prep<<<1, 256>>>(W1, W2, W3);
    k_stage1<<<NE/128, 256, STAGE_SMEM>>>(signal, edges, efeat);
    k_finalize<<<1, 256>>>(g1, b1);
    k_stage<0><<<NE/128, 256, STAGE_SMEM>>>(0);
    k_finalize<<<1, 256>>>(g2, b2);
    k_stage<1><<<NE/128, 256, STAGE_SMEM>>>(1);
    k_finalize<<<1, 256>>>(g3, b3);
    k_out<<<(NP*16)/256, 256>>>(out);
}

// round 16
// speedup vs baseline: 1.3649x; 1.1272x over previous
#include <cuda_runtime.h>
#include <cuda_fp16.h>
#include <math.h>

#define NB    4
#define NPTS  8192
#define NP    (NB*NPTS)          /* 32768 points */
#define KNN   32
#define NE    (NB*NPTS*KNN)      /* 1048576 edges */
#define EPB   (NPTS*KNN)         /* 262144 edges per batch */
#define BC    256
#define CNTF  ((float)EPB)
#define EPSV  1e-5f
#define SLOPE 0.1f

// Y fp16, granule-major: granule q (0..7) = channels [8q,8q+8) of an edge,
// stored as uint4 (4 half2 words).
__device__ __align__(16) unsigned g_Y16[(size_t)32 * NE];
__device__ __align__(16) float g_sum[BC], g_sumsq[BC], g_s[BC], g_t[BC];
// pre-split weights (fp16x2 hi/lo)
__device__ __align__(16) unsigned g_Wh[2][2048], g_Wl[2][2048];
__device__ __align__(16) unsigned g_W1h[64*18], g_W1l[64*18];
// stage-3 pooled raw y: [point][64ch], max and min
__device__ __align__(16) float g_Pmx[(size_t)NP*64], g_Pmn[(size_t)NP*64];

// ---------------------------------------------------------------- helpers
// split two floats into packed fp16x2 hi + fp16x2 lo
__device__ __forceinline__ uint2 split2h(float x0, float x1) {
    __half2 h = __floats2half2_rn(x0, x1);
    float2 hf = __half22float2(h);
    __half2 l = __floats2half2_rn(x0 - hf.x, x1 - hf.y);
    uint2 r;
    r.x = *(unsigned*)&h; r.y = *(unsigned*)&l;
    return r;
}
__device__ __forceinline__ void mma16(float* c,
                                      unsigned a0, unsigned a1, unsigned a2, unsigned a3,
                                      unsigned b0, unsigned b1) {
    asm("mma.sync.aligned.m16n8k16.row.col.f32.f16.f16.f32 "
        "{%0,%1,%2,%3},{%4,%5,%6,%7},{%8,%9},{%0,%1,%2,%3};"
        : "+f"(c[0]), "+f"(c[1]), "+f"(c[2]), "+f"(c[3])
        : "r"(a0), "r"(a1), "r"(a2), "r"(a3), "r"(b0), "r"(b1));
}
__device__ __forceinline__ void ldsm4(unsigned& r0, unsigned& r1,
                                      unsigned& r2, unsigned& r3, unsigned a) {
    asm volatile("ldmatrix.sync.aligned.m8n8.x4.shared.b16 {%0,%1,%2,%3}, [%4];"
        : "=r"(r0), "=r"(r1), "=r"(r2), "=r"(r3) : "r"(a));
}
__device__ __forceinline__ unsigned s2u(const void* p) {
    return (unsigned)__cvta_generic_to_shared(p);
}

// -------------------------------- prep: zero stats + pre-split all weights
__global__ void k_prep(const float* __restrict__ W1,
                       const float* __restrict__ W2,
                       const float* __restrict__ W3) {
    int tid = threadIdx.x;
    if (tid < BC) { g_sum[tid] = 0.f; g_sumsq[tid] = 0.f; }
    for (int p = tid; p < 2048; p += 256) {
        int o = p >> 5, cp = p & 31;
        float2 w2 = *(const float2*)&W2[o*64 + 2*cp];
        uint2 a = split2h(w2.x, w2.y);
        g_Wh[0][p] = a.x; g_Wl[0][p] = a.y;
        float2 w3 = *(const float2*)&W3[o*64 + 2*cp];
        uint2 b = split2h(w3.x, w3.y);
        g_Wh[1][p] = b.x; g_Wl[1][p] = b.y;
    }
    for (int p = tid; p < 64*18; p += 256) {
        int o = p / 18, cp = p - o*18;
        float w0, w1;
        if (cp < 17)      { w0 = W1[o*35 + 2*cp]; w1 = W1[o*35 + 2*cp + 1]; }
        else              { w0 = W1[o*35 + 34];   w1 = 0.f; }
        uint2 hl = split2h(w0, w1);
        g_W1h[p] = hl.x; g_W1l[p] = hl.y;
    }
}

// ------ shared stats piece: warp-reduce s/q, atomics into sStat, then global
__device__ __forceinline__ void stats_reduce(float acc[2][4][4], int b, float* sStat) {
    int tid = threadIdx.x;
    int lane = tid & 31, wid = tid >> 5;
    int n0 = (wid >> 2) * 32;
    float s8[8], q8[8];
    #pragma unroll
    for (int nt = 0; nt < 4; nt++) {
        #pragma unroll
        for (int par = 0; par < 2; par++) {
            float a = acc[0][nt][par],   c = acc[0][nt][par+2];
            float d = acc[1][nt][par],   e = acc[1][nt][par+2];
            s8[nt*2+par] = (a + c) + (d + e);
            q8[nt*2+par] = fmaf(a,a, fmaf(c,c, fmaf(d,d, e*e)));
        }
    }
    #pragma unroll
    for (int off = 16; off >= 4; off >>= 1) {
        #pragma unroll
        for (int i = 0; i < 8; i++) {
            s8[i] += __shfl_down_sync(0xffffffffu, s8[i], off);
            q8[i] += __shfl_down_sync(0xffffffffu, q8[i], off);
        }
    }
    if (lane < 4) {
        #pragma unroll
        for (int nt = 0; nt < 4; nt++) {
            #pragma unroll
            for (int par = 0; par < 2; par++) {
                int ch = n0 + nt*8 + 2*lane + par;
                atomicAdd(&sStat[ch], s8[nt*2+par]);
                atomicAdd(&sStat[64+ch], q8[nt*2+par]);
            }
        }
    }
    __syncthreads();
    if (tid < 128) {
        float v = sStat[tid];
        if (tid < 64) atomicAdd(&g_sum[b*64 + tid], v);
        else          atomicAdd(&g_sumsq[b*64 + tid - 64], v);
    }
}

// ------ epilogue A: store fp16 Y (granule layout, coalesced) + stats
__device__ __forceinline__ void mma_epilogue(float acc[2][4][4], size_t bb, int b,
                                             float* sStat) {
    int tid = threadIdx.x;
    int lane = tid & 31, wid = tid >> 5;
    int gid = lane >> 2, tig = lane & 3;
    int m0 = (wid & 3) * 32, n0 = (wid >> 2) * 32;
    #pragma unroll
    for (int mt = 0; mt < 2; mt++) {
        #pragma unroll
        for (int nt = 0; nt < 4; nt++) {
            int qn = (n0 >> 3) + nt;                  // granule
            size_t eg = bb + m0 + mt*16 + gid;
            __half2 h01 = __floats2half2_rn(acc[mt][nt][0], acc[mt][nt][1]);
            __half2 h23 = __floats2half2_rn(acc[mt][nt][2], acc[mt][nt][3]);
            size_t w0 = ((size_t)qn*NE + eg)*4 + tig;
            g_Y16[w0]      = *(unsigned*)&h01;        // edge eg
            g_Y16[w0 + 32] = *(unsigned*)&h23;        // edge eg+8
        }
    }
    stats_reduce(acc, b, sStat);
}

// ------ epilogue B: pooled min/max per point (stage 3; skips Y entirely)
__device__ __forceinline__ void mma_epilogue_pool(float acc[2][4][4], size_t bp, int b,
                                                  float* sStat) {
    int tid = threadIdx.x;
    int lane = tid & 31, wid = tid >> 5;
    int n0 = (wid >> 2) * 32, wm = wid & 3;
    float mx8[8], mn8[8];
    #pragma unroll
    for (int nt = 0; nt < 4; nt++) {
        #pragma unroll
        for (int par = 0; par < 2; par++) {
            float a = acc[0][nt][par],   c = acc[0][nt][par+2];
            float d = acc[1][nt][par],   e = acc[1][nt][par+2];
            mx8[nt*2+par] = fmaxf(fmaxf(a,c), fmaxf(d,e));
            mn8[nt*2+par] = fminf(fminf(a,c), fminf(d,e));
        }
    }
    #pragma unroll
    for (int off = 16; off >= 4; off >>= 1) {
        #pragma unroll
        for (int i = 0; i < 8; i++) {
            mx8[i] = fmaxf(mx8[i], __shfl_down_sync(0xffffffffu, mx8[i], off));
            mn8[i] = fminf(mn8[i], __shfl_down_sync(0xffffffffu, mn8[i], off));
        }
    }
    if (lane < 4) {
        size_t pt = bp + wm;
        #pragma unroll
        for (int nt = 0; nt < 4; nt++) {
            #pragma unroll
            for (int par = 0; par < 2; par++) {
                int ch = n0 + nt*8 + 2*lane + par;
                g_Pmx[pt*64 + ch] = mx8[nt*2+par];
                g_Pmn[pt*64 + ch] = mn8[nt*2+par];
            }
        }
    }
    stats_reduce(acc, b, sStat);
}

// smem: X fp16 single plane, swizzled (row=128B, granule XOR row&7); W stride 36
#define OFF_XH 0
#define OFF_WH 4096
#define OFF_WL (4096 + 64*36)
#define OFF_ST (4096 + 128*36)
#define STAGE_SMEM ((OFF_ST + 128) * (int)sizeof(unsigned))
#define PSTR 36   /* W rows only */

// ---------------- fp16 2-term mma mainloop (swizzled-X LDSM loads) --------
template<int NCHUNK>
__device__ __forceinline__ void mma_main(const unsigned* sm, float acc[2][4][4]) {
    int tid = threadIdx.x;
    int lane = tid & 31, wid = tid >> 5;
    int m0 = (wid & 3) * 32, n0 = (wid >> 2) * 32;
    int g = lane >> 3, lr = lane & 7;

    // A: swizzled X rows (128B/row)
    int arow = m0 + lr + (g & 1)*8;
    int r7 = arow & 7;
    int gbase = g >> 1;
    unsigned rowH = s2u(sm) + arow*128;
    // B: W region, stride 36 words
    int brow = n0 + lr + (g >> 1)*8;
    int bcol = (g & 1)*4;
    unsigned bH0 = s2u(sm + OFF_WH + brow*PSTR + bcol);
    unsigned bH1 = bH0 + 16*PSTR*4;
    unsigned bL0 = bH0 + 64*PSTR*4;
    unsigned bL1 = bH1 + 64*PSTR*4;

    #pragma unroll
    for (int mt = 0; mt < 2; mt++)
        #pragma unroll
        for (int nt = 0; nt < 4; nt++)
            #pragma unroll
            for (int r = 0; r < 4; r++) acc[mt][nt][r] = 0.f;

    #pragma unroll
    for (int ks = 0; ks < NCHUNK; ks++) {
        unsigned gax = (unsigned)((gbase + 2*ks) ^ r7) << 4;   // swizzled granule byte off
        unsigned boff = ks*32;
        unsigned ah[2][4], bh[4][2], bl[4][2];
        ldsm4(ah[0][0], ah[0][1], ah[0][2], ah[0][3], rowH + gax);
        ldsm4(ah[1][0], ah[1][1], ah[1][2], ah[1][3], rowH + gax + 16*128);
        ldsm4(bh[0][0], bh[0][1], bh[1][0], bh[1][1], bH0 + boff);
        ldsm4(bh[2][0], bh[2][1], bh[3][0], bh[3][1], bH1 + boff);
        ldsm4(bl[0][0], bl[0][1], bl[1][0], bl[1][1], bL0 + boff);
        ldsm4(bl[2][0], bl[2][1], bl[3][0], bl[3][1], bL1 + boff);
        #pragma unroll
        for (int mt = 0; mt < 2; mt++)
            #pragma unroll
            for (int nt = 0; nt < 4; nt++) {
                mma16(acc[mt][nt], ah[mt][0],ah[mt][1],ah[mt][2],ah[mt][3], bh[nt][0],bh[nt][1]);
                mma16(acc[mt][nt], ah[mt][0],ah[mt][1],ah[mt][2],ah[mt][3], bl[nt][0],bl[nt][1]);
            }
    }
}

// ------- stage 1: gather + concat + GEMM1 (K=35 padded to 48, 3 chunks)
__global__ void __launch_bounds__(256) k_stage1(
    const float* __restrict__ signal, const int* __restrict__ edges,
    const float* __restrict__ efeat)
{
    extern __shared__ unsigned sm[];
    float* sStat = (float*)(sm + OFF_ST);

    int tid = threadIdx.x;
    int b = blockIdx.x >> 11;
    size_t bb = (size_t)blockIdx.x * 128;

    // W1: pre-split pairs [64][18] into stride-36 rows + zero pads 18..23
    #pragma unroll
    for (int i = tid; i < 64*9; i += 256) {
        int o = i / 9, j = i - o*9;
        uint2 h = *(const uint2*)&g_W1h[o*18 + j*2];
        uint2 l = *(const uint2*)&g_W1l[o*18 + j*2];
        *(uint2*)&sm[OFF_WH + o*PSTR + j*2] = h;
        *(uint2*)&sm[OFF_WL + o*PSTR + j*2] = l;
    }
    for (int i = tid; i < 64*6; i += 256) {
        int o = i / 6, cp = 18 + (i - (i/6)*6);
        sm[OFF_WH + o*PSTR + cp] = 0u; sm[OFF_WL + o*PSTR + cp] = 0u;
    }
    if (tid < 128) sStat[tid] = 0.f;

    // gather: 2 threads per edge, 16 floats each -> 2 swizzled fp16 granules
    {
        int eL = tid >> 1, part = tid & 1;
        int idx = edges[bb + eL];
        const float4* src = (const float4*)signal + (size_t)idx*8 + part*4;
        float4 v0 = src[0], v1 = src[1], v2 = src[2], v3 = src[3];
        __half2 p0 = __floats2half2_rn(v0.x, v0.y), p1 = __floats2half2_rn(v0.z, v0.w);
        __half2 p2 = __floats2half2_rn(v1.x, v1.y), p3 = __floats2half2_rn(v1.z, v1.w);
        __half2 p4 = __floats2half2_rn(v2.x, v2.y), p5 = __floats2half2_rn(v2.z, v2.w);
        __half2 p6 = __floats2half2_rn(v3.x, v3.y), p7 = __floats2half2_rn(v3.z, v3.w);
        int e7 = eL & 7;
        unsigned wbase = eL*32;
        unsigned w0 = wbase + (((part*2 + 0) ^ e7) << 2);
        unsigned w1 = wbase + (((part*2 + 1) ^ e7) << 2);
        *(uint4*)&sm[OFF_XH + w0] = make_uint4(*(unsigned*)&p0, *(unsigned*)&p1,
                                               *(unsigned*)&p2, *(unsigned*)&p3);
        *(uint4*)&sm[OFF_XH + w1] = make_uint4(*(unsigned*)&p4, *(unsigned*)&p5,
                                               *(unsigned*)&p6, *(unsigned*)&p7);
    }
    if (tid < 128) {  // edge feats -> granule 4 (ch 32..39); granule 5 = 0
        size_t base = 3*(bb + tid);
        float f0 = efeat[base], f1 = efeat[base+1], f2 = efeat[base+2];
        __half2 h0 = __floats2half2_rn(f0, f1);
        __half2 h1 = __floats2half2_rn(f2, 0.f);
        int e7 = tid & 7;
        unsigned wbase = tid*32;
        unsigned w4 = wbase + ((4 ^ e7) << 2);
        unsigned w5 = wbase + ((5 ^ e7) << 2);
        *(uint4*)&sm[OFF_XH + w4] = make_uint4(*(unsigned*)&h0, *(unsigned*)&h1, 0u, 0u);
        *(uint4*)&sm[OFF_XH + w5] = make_uint4(0u, 0u, 0u, 0u);
    }
    __syncthreads();

    float acc[2][4][4];
    mma_main<3>(sm, acc);
    mma_epilogue(acc, bb, b, sStat);
}

// ------------------------------------- stats -> (scale, shift), reset accum
__global__ void k_finalize(const float* __restrict__ gam, const float* __restrict__ bet) {
    int i = threadIdx.x;
    float mean = g_sum[i]   * (1.f/CNTF);
    float var  = g_sumsq[i] * (1.f/CNTF) - mean*mean;
    float sc   = gam[i & 63] * rsqrtf(var + EPSV);
    g_s[i] = sc;
    g_t[i] = bet[i & 63] - mean * sc;
    g_sum[i] = 0.f; g_sumsq[i] = 0.f;
}

// ------- stages 2/3: norm + leaky + 64x64 GEMM (K=64, 4 chunks)
template<int POOL>
__global__ void __launch_bounds__(256, 4) k_stage(int wsel) {
    extern __shared__ unsigned sm[];
    float* sStat = (float*)(sm + OFF_ST);

    int tid = threadIdx.x;
    int b = blockIdx.x >> 11;
    size_t bb = (size_t)blockIdx.x * 128;

    const unsigned* wh = g_Wh[wsel];
    const unsigned* wl = g_Wl[wsel];
    #pragma unroll
    for (int i = tid; i < 512; i += 256) {
        int o = i >> 3, j = i & 7;
        uint4 h = *(const uint4*)&wh[o*32 + j*4];
        uint4 l = *(const uint4*)&wl[o*32 + j*4];
        *(uint4*)&sm[OFF_WH + o*PSTR + j*4] = h;
        *(uint4*)&sm[OFF_WL + o*PSTR + j*4] = l;
    }
    if (tid < 128) sStat[tid] = 0.f;

    // X: vector-load fp16 granules, normalize + leaky, fp16, swizzled STS.128
    #pragma unroll
    for (int it = 0; it < 4; it++) {
        int i = it*256 + tid;
        int q = i >> 7, eL = i & 127;
        uint4 v = ((const uint4*)g_Y16)[(size_t)q*NE + bb + eL];
        float4 sA = __ldg(&((const float4*)g_s)[b*16 + 2*q]);
        float4 sB = __ldg(&((const float4*)g_s)[b*16 + 2*q + 1]);
        float4 tA = __ldg(&((const float4*)g_t)[b*16 + 2*q]);
        float4 tB = __ldg(&((const float4*)g_t)[b*16 + 2*q + 1]);
        float2 f0 = __half22float2(*(__half2*)&v.x);
        float2 f1 = __half22float2(*(__half2*)&v.y);
        float2 f2 = __half22float2(*(__half2*)&v.z);
        float2 f3 = __half22float2(*(__half2*)&v.w);
        float x0 = fmaf(f0.x, sA.x, tA.x); x0 = (x0>=0.f)?x0:SLOPE*x0;
        float x1 = fmaf(f0.y, sA.y, tA.y); x1 = (x1>=0.f)?x1:SLOPE*x1;
        float x2 = fmaf(f1.x, sA.z, tA.z); x2 = (x2>=0.f)?x2:SLOPE*x2;
        float x3 = fmaf(f1.y, sA.w, tA.w); x3 = (x3>=0.f)?x3:SLOPE*x3;
        float x4 = fmaf(f2.x, sB.x, tB.x); x4 = (x4>=0.f)?x4:SLOPE*x4;
        float x5 = fmaf(f2.y, sB.y, tB.y); x5 = (x5>=0.f)?x5:SLOPE*x5;
        float x6 = fmaf(f3.x, sB.z, tB.z); x6 = (x6>=0.f)?x6:SLOPE*x6;
        float x7 = fmaf(f3.y, sB.w, tB.w); x7 = (x7>=0.f)?x7:SLOPE*x7;
        __half2 p0 = __floats2half2_rn(x0, x1), p1 = __floats2half2_rn(x2, x3);
        __half2 p2 = __floats2half2_rn(x4, x5), p3 = __floats2half2_rn(x6, x7);
        unsigned wrd = eL*32 + ((q ^ (eL & 7)) << 2);
        *(uint4*)&sm[OFF_XH + wrd] = make_uint4(*(unsigned*)&p0, *(unsigned*)&p1,
                                                 *(unsigned*)&p2, *(unsigned*)&p3);
    }
    __syncthreads();

    float acc[2][4][4];
    mma_main<4>(sm, acc);
    if (POOL) mma_epilogue_pool(acc, (size_t)blockIdx.x * 4, b, sStat);
    else      mma_epilogue(acc, bb, b, sStat);
}

// -------- final: norm3 + leaky on pooled extrema, direct (B,N,64) store
__global__ void __launch_bounds__(256) k_out(float* __restrict__ out) {
    int tid = blockIdx.x * 256 + threadIdx.x;    // over NP*16 float4s
    int c4 = tid & 15;
    int pt = tid >> 4;
    int b  = pt >> 13;
    float4 sc = ((const float4*)g_s)[b*16 + c4];
    float4 tt = ((const float4*)g_t)[b*16 + c4];
    float4 mx = ((const float4*)g_Pmx)[tid];
    float4 mn = ((const float4*)g_Pmn)[tid];
    float4 y;
    y.x = fmaf((sc.x>=0.f)?mx.x:mn.x, sc.x, tt.x); y.x = (y.x>=0.f)?y.x:SLOPE*y.x;
    y.y = fmaf((sc.y>=0.f)?mx.y:mn.y, sc.y, tt.y); y.y = (y.y>=0.f)?y.y:SLOPE*y.y;
    y.z = fmaf((sc.z>=0.f)?mx.z:mn.z, sc.z, tt.z); y.z = (y.z>=0.f)?y.z:SLOPE*y.z;
    y.w = fmaf((sc.w>=0.f)?mx.w:mn.w, sc.w, tt.w); y.w = (y.w>=0.f)?y.w:SLOPE*y.w;
    ((float4*)out)[tid] = y;
}

// ---------------------------------------------------------------------------
extern "C" void kernel_launch(void* const* d_in, const int* in_sizes, int n_in,
                              void* d_out, int out_size)
{
    const float* signal = (const float*)d_in[0];
    const int*   edges  = (const int*)d_in[1];
    const float* efeat  = (const float*)d_in[2];
    // d_in[3] = k (constant 32, baked in)
    const float* W1 = (const float*)d_in[4];
    const float* g1 = (const float*)d_in[5];
    const float* b1 = (const float*)d_in[6];
    const float* W2 = (const float*)d_in[7];
    const float* g2 = (const float*)d_in[8];
    const float* b2 = (const float*)d_in[9];
    const float* W3 = (const float*)d_in[10];
    const float* g3 = (const float*)d_in[11];
    const float* b3 = (const float*)d_in[12];
    float* out = (float*)d_out;

    cudaFuncSetAttribute(k_stage1,   cudaFuncAttributeMaxDynamicSharedMemorySize, STAGE_SMEM);
    cudaFuncSetAttribute(k_stage<0>, cudaFuncAttributeMaxDynamicSharedMemorySize, STAGE_SMEM);
    cudaFuncSetAttribute(k_stage<1>, cudaFuncAttributeMaxDynamicSharedMemorySize, STAGE_SMEM);

    k_prep<<<1, 256>>>(W1, W2, W3);
    k_stage1<<<NE/128, 256, STAGE_SMEM>>>(signal, edges, efeat);
    k_finalize<<<1, 256>>>(g1, b1);
    k_stage<0><<<NE/128, 256, STAGE_SMEM>>>(0);
    k_finalize<<<1, 256>>>(g2, b2);
    k_stage<1><<<NE/128, 256, STAGE_SMEM>>>(1);
    k_finalize<<<1, 256>>>(g3, b3);
    k_out<<<(NP*16)/256, 256>>>(out);
}